// round 6
// baseline (speedup 1.0000x reference)
#include <cuda_runtime.h>
#include <cstdint>
#include <math.h>

// ---------------------------------------------------------------------------
// Problem constants
// ---------------------------------------------------------------------------
constexpr int Bc = 8;
constexpr int C  = 1024;
constexpr int Ci = 512;
constexpr int Nd = 48 * 48;          // 2304
constexpr int Na = 16 * 16;          // 256
constexpr int R  = 64;               // C / 16
constexpr float BN_INV = 0.9999950000374997f;  // 1/sqrt(1+1e-5)

// ---------------------------------------------------------------------------
// Device scratch (static)
// ---------------------------------------------------------------------------
__device__ float g_detT  [Bc * Nd * C];
__device__ float g_aimT  [Bc * Na * C];
__device__ float g_dx    [Bc * Ci * Nd];
__device__ float g_phx   [Bc * Nd * Ci];
__device__ float g_ax    [Bc * Ci * Na];
__device__ float g_thx   [Bc * Na * Ci];
__device__ float g_fm    [Bc * Na * Nd];
__device__ float g_fT    [Bc * Nd * Na];
__device__ float g_nap   [Bc * Na * Ci];
__device__ float g_ndp   [Bc * Nd * Ci];
__device__ float g_nonaim[Bc * C  * Na];
__device__ float g_pooled[Bc * 2  * C];

// ---------------------------------------------------------------------------
// helpers
// ---------------------------------------------------------------------------
__device__ __forceinline__ uint32_t f2tf(float x) {
    uint32_t r;
    asm("cvt.rna.tf32.f32 %0, %1;" : "=r"(r) : "f"(x));
    return r;
}
__device__ __forceinline__ void mma8(float* d, const uint32_t* a, const uint32_t* b) {
    asm volatile(
        "mma.sync.aligned.m16n8k8.row.col.f32.tf32.tf32.f32 "
        "{%0,%1,%2,%3}, {%4,%5,%6,%7}, {%8,%9}, {%0,%1,%2,%3};"
        : "+f"(d[0]), "+f"(d[1]), "+f"(d[2]), "+f"(d[3])
        : "r"(a[0]), "r"(a[1]), "r"(a[2]), "r"(a[3]), "r"(b[0]), "r"(b[1]));
}

// ---------------------------------------------------------------------------
// tf32 mma.sync GEMM:  D[M,N] = alpha * A[M,K] * B[N,K]^T  (+ epilogue)
//   Block 128 x (WN*64), 2*WN warps (2m x WNn), warp tile 64x64, BK=16
//   double-buffered, register-staged LDG -> cvt.rna -> STS (single sync/iter).
//   Smem k-stride 20 words: fragment bank = 20g+t, conflict-free.
//   Requires M%128==0, N%(WN*64)==0, K%16==0, row strides == K.
//   EPI 0: alpha*acc (+ bM[m] if BMODE==1, + bN[n] if BMODE==2)
//   EPI 1: bng[m]*BN_INV*(acc+bM[m]) + bnb[m] + resid[m*ldc+n]
//   EPI 2: EPI1 value v; additionally out2 = v * cw[bz*M + m]
// ---------------------------------------------------------------------------
constexpr int SA = 20;               // padded k-stride in words (16 + 4)

template<int EPI, int BMODE, int WN>
__global__ void __launch_bounds__(WN * 64)
tgemm(const float* __restrict__ A, const float* __restrict__ B,
      float* __restrict__ Co,
      int K, int ldc, long strA, long strB, long strC, float alpha,
      const float* __restrict__ bM, const float* __restrict__ bN,
      const float* __restrict__ bng, const float* __restrict__ bnb,
      const float* __restrict__ resid, long sR,
      const float* __restrict__ cw, float* __restrict__ out2)
{
    constexpr int NT     = WN * 64;            // block N
    constexpr int AWORDS = 128 * SA;
    constexpr int STAGE  = (128 + NT) * SA;    // words per stage (A then B)

    extern __shared__ uint32_t sm[];

    const int tid = threadIdx.x, lane = tid & 31, wid = tid >> 5;
    const int wm = wid & 1, wn = wid >> 1;     // warp grid 2(m) x WN(n)
    const int bz = blockIdx.z;
    const int bm = blockIdx.y * 128, bn = blockIdx.x * NT;

    // ---- loader addressing ----
    // B: thread t -> row t (NT == threads), 16 floats.
    // A: WN==4: thread t -> row t/2, k-half (t&1)*8 (8 floats).
    //    WN==2: thread t -> row t, 16 floats.
    const float* bpg = B + (long)bz * strB + (long)(bn + tid) * K;
    const float* apg;
    int a_sm_word;
    if constexpr (WN == 4) {
        apg = A + (long)bz * strA + (long)(bm + (tid >> 1)) * K + (tid & 1) * 8;
        a_sm_word = (tid >> 1) * SA + (tid & 1) * 8;
    } else {
        apg = A + (long)bz * strA + (long)(bm + tid) * K;
        a_sm_word = tid * SA;
    }
    const int b_sm_word = AWORDS + tid * SA;

    float4 rA[4], rB[4];
    auto g2r = [&](int kt) {
        const float* ap = apg + kt * 16;
        const float* bp = bpg + kt * 16;
        if constexpr (WN == 4) {
            rA[0] = *(const float4*)ap; rA[1] = *(const float4*)(ap + 4);
        } else {
            #pragma unroll
            for (int j = 0; j < 4; j++) rA[j] = *(const float4*)(ap + j * 4);
        }
        #pragma unroll
        for (int j = 0; j < 4; j++) rB[j] = *(const float4*)(bp + j * 4);
    };
    auto r2s = [&](int st) {
        uint32_t* as = sm + st * STAGE + a_sm_word;
        uint32_t* bs = sm + st * STAGE + b_sm_word;
        constexpr int na = (WN == 4) ? 2 : 4;
        #pragma unroll
        for (int j = 0; j < na; j++)
            *(uint4*)(as + j * 4) = make_uint4(f2tf(rA[j].x), f2tf(rA[j].y),
                                               f2tf(rA[j].z), f2tf(rA[j].w));
        #pragma unroll
        for (int j = 0; j < 4; j++)
            *(uint4*)(bs + j * 4) = make_uint4(f2tf(rB[j].x), f2tf(rB[j].y),
                                               f2tf(rB[j].z), f2tf(rB[j].w));
    };

    float acc[4][8][4];
    #pragma unroll
    for (int i = 0; i < 4; i++)
        #pragma unroll
        for (int j = 0; j < 8; j++)
            #pragma unroll
            for (int q = 0; q < 4; q++) acc[i][j][q] = 0.f;

    const int g = lane >> 2, t = lane & 3;
    auto compute = [&](int st) {
        const uint32_t* sAp = sm + st * STAGE;
        const uint32_t* sBp = sAp + AWORDS;
        #pragma unroll
        for (int k8 = 0; k8 < 2; k8++) {
            const int kb = k8 * 8;
            uint32_t af[4][4];
            #pragma unroll
            for (int mi = 0; mi < 4; mi++) {
                const uint32_t* p = sAp + (wm * 64 + mi * 16 + g) * SA + kb + t;
                af[mi][0] = p[0];
                af[mi][1] = p[8 * SA];
                af[mi][2] = p[4];
                af[mi][3] = p[8 * SA + 4];
            }
            #pragma unroll
            for (int ni = 0; ni < 8; ni++) {
                const uint32_t* p = sBp + (wn * 64 + ni * 8 + g) * SA + kb + t;
                uint32_t bf[2] = { p[0], p[4] };
                #pragma unroll
                for (int mi = 0; mi < 4; mi++) mma8(acc[mi][ni], af[mi], bf);
            }
        }
    };

    const int nk = K / 16;
    g2r(0); r2s(0);
    __syncthreads();
    for (int kt = 0; kt < nk; kt++) {
        const int s = kt & 1;
        if (kt + 1 < nk) g2r(kt + 1);      // LDG latency overlaps compute
        compute(s);
        if (kt + 1 < nk) r2s(s ^ 1);       // stage s^1 fully drained (sync @ kt-1)
        __syncthreads();
    }

    // ---- epilogue ----
    const int t2 = (lane & 3) * 2;
    #pragma unroll
    for (int mi = 0; mi < 4; mi++) {
        #pragma unroll
        for (int half = 0; half < 2; half++) {
            const int m = bm + wm * 64 + mi * 16 + half * 8 + g;
            float addM = 0.f, sc = 1.f, be = 0.f, gwv = 0.f;
            if constexpr (EPI == 0) {
                if constexpr (BMODE == 1) addM = bM[m];
            } else {
                addM = bM[m]; sc = bng[m] * BN_INV; be = bnb[m];
            }
            float* crow = Co + (long)bz * strC + (long)m * ldc;
            const float* rrow = nullptr;
            float* o2row = nullptr;
            if constexpr (EPI >= 1) rrow = resid + (long)bz * sR + (long)m * ldc;
            if constexpr (EPI == 2) {
                o2row = out2 + (long)bz * strC + (long)m * ldc;
                gwv = cw[(long)bz * (gridDim.y * 128) + m];
            }
            #pragma unroll
            for (int ni = 0; ni < 8; ni++) {
                const int n = bn + wn * 64 + ni * 8 + t2;
                const float c0 = acc[mi][ni][half * 2 + 0];
                const float c1 = acc[mi][ni][half * 2 + 1];
                float2 o;
                if constexpr (EPI == 0) {
                    o.x = alpha * c0 + addM;
                    o.y = alpha * c1 + addM;
                    if constexpr (BMODE == 2) { o.x += bN[n]; o.y += bN[n + 1]; }
                } else {
                    float2 rv = *(const float2*)&rrow[n];
                    o.x = sc * (c0 + addM) + be + rv.x;
                    o.y = sc * (c1 + addM) + be + rv.y;
                }
                *(float2*)&crow[n] = o;
                if constexpr (EPI == 2) {
                    float2 o2 = { o.x * gwv, o.y * gwv };
                    *(float2*)&o2row[n] = o2;
                }
            }
        }
    }
}

constexpr int GS4 = 2 * (128 + 256) * SA * 4;   // 61440 B
constexpr int GS2 = 2 * (128 + 128) * SA * 4;   // 40960 B

// ---------------------------------------------------------------------------
// Transpose: src [rows][cols] -> dst [cols][rows], per batch z
// ---------------------------------------------------------------------------
__global__ void transpose_k(const float* __restrict__ src, float* __restrict__ dst,
                            int rows, int cols)
{
    __shared__ float t[32][33];
    const long bo = (long)blockIdx.z * rows * cols;
    const int c0 = blockIdx.x * 32, r0 = blockIdx.y * 32;
    const int tx = threadIdx.x, ty = threadIdx.y;
    #pragma unroll
    for (int i = 0; i < 32; i += 8)
        t[ty + i][tx] = src[bo + (long)(r0 + ty + i) * cols + c0 + tx];
    __syncthreads();
    #pragma unroll
    for (int i = 0; i < 32; i += 8)
        dst[bo + (long)(c0 + ty + i) * rows + r0 + tx] = t[tx][ty + i];
}

// ---------------------------------------------------------------------------
// Avg+Max pooling: one warp per (b,c)
// ---------------------------------------------------------------------------
__global__ void pool_k(const float* __restrict__ na, float* __restrict__ pooled)
{
    const int gw = (int)((blockIdx.x * (long)blockDim.x + threadIdx.x) >> 5);
    const int lane = threadIdx.x & 31;
    if (gw >= Bc * C) return;
    const float* p = na + (long)gw * Na;
    float s = 0.f, m = -3.4e38f;
    for (int i = lane; i < Na; i += 32) { float v = p[i]; s += v; m = fmaxf(m, v); }
    #pragma unroll
    for (int o = 16; o; o >>= 1) {
        s += __shfl_xor_sync(0xffffffffu, s, o);
        m = fmaxf(m, __shfl_xor_sync(0xffffffffu, m, o));
    }
    if (lane == 0) {
        const int b = gw / C, c = gw % C;
        pooled[(long)b * 2 * C + c]     = s * (1.f / Na);
        pooled[(long)b * 2 * C + C + c] = m;
    }
}

// ---------------------------------------------------------------------------
// Channel gate MLP + sigmoid, one block per batch
// ---------------------------------------------------------------------------
__global__ void gate_k(const float* __restrict__ pooled,
                       const float* __restrict__ w1, const float* __restrict__ b1,
                       const float* __restrict__ w2, const float* __restrict__ b2,
                       float* __restrict__ cw)
{
    __shared__ float sv[2 * C];
    __shared__ float h[2][R];
    __shared__ float hs[R];
    const int b = blockIdx.x, tid = threadIdx.x;
    for (int i = tid; i < 2 * C; i += blockDim.x)
        sv[i] = pooled[(long)b * 2 * C + i];
    __syncthreads();
    if (tid < 2 * R) {
        const int which = tid / R, r = tid % R;
        const float* v = sv + which * C;
        const float* wr = w1 + r * C;
        float acc = b1[r];
        for (int c = 0; c < C; c++) acc += wr[c] * v[c];
        h[which][r] = fmaxf(acc, 0.f);
    }
    __syncthreads();
    if (tid < R) hs[tid] = h[0][tid] + h[1][tid];
    __syncthreads();
    for (int c = tid; c < C; c += blockDim.x) {
        const float* wc = w2 + c * R;
        float acc = 2.f * b2[c];
        #pragma unroll 8
        for (int r = 0; r < R; r++) acc += wc[r] * hs[r];
        cw[(long)b * C + c] = 1.f / (1.f + expf(-acc));
    }
}

// ---------------------------------------------------------------------------
// Channel scaling (act_aim): dst = src * cw[b*C + c]
// ---------------------------------------------------------------------------
__global__ void scale_k(const float* __restrict__ src, const float* __restrict__ cw,
                        float* __restrict__ dst, int q_div, long total4)
{
    const long i = blockIdx.x * (long)blockDim.x + threadIdx.x;
    if (i >= total4) return;
    const float w = cw[i / q_div];
    float4 v = ((const float4*)src)[i];
    v.x *= w; v.y *= w; v.z *= w; v.w *= w;
    ((float4*)dst)[i] = v;
}

// ---------------------------------------------------------------------------
// Launch
// ---------------------------------------------------------------------------
extern "C" void kernel_launch(void* const* d_in, const int* in_sizes, int n_in,
                              void* d_out, int out_size)
{
    (void)in_sizes; (void)n_in; (void)out_size;
    const float* detect = (const float*)d_in[0];
    const float* aim    = (const float*)d_in[1];
    const float* g_w    = (const float*)d_in[2];
    const float* g_b    = (const float*)d_in[3];
    const float* th_w   = (const float*)d_in[4];
    const float* th_b   = (const float*)d_in[5];
    const float* ph_w   = (const float*)d_in[6];
    const float* ph_b   = (const float*)d_in[7];
    const float* W_w    = (const float*)d_in[8];
    const float* W_b    = (const float*)d_in[9];
    const float* W_bn_g = (const float*)d_in[10];
    const float* W_bn_b = (const float*)d_in[11];
    const float* Q_w    = (const float*)d_in[12];
    const float* Q_b    = (const float*)d_in[13];
    const float* Q_bn_g = (const float*)d_in[14];
    const float* Q_bn_b = (const float*)d_in[15];
    const float* m1_w   = (const float*)d_in[16];
    const float* m1_b   = (const float*)d_in[17];
    const float* m2_w   = (const float*)d_in[18];
    const float* m2_b   = (const float*)d_in[19];
    float* out = (float*)d_out;

    float *detT, *aimT, *dx, *phx, *ax, *thx, *fm, *fT, *nap, *ndp, *nonaim, *pooled;
    cudaGetSymbolAddress((void**)&detT,   g_detT);
    cudaGetSymbolAddress((void**)&aimT,   g_aimT);
    cudaGetSymbolAddress((void**)&dx,     g_dx);
    cudaGetSymbolAddress((void**)&phx,    g_phx);
    cudaGetSymbolAddress((void**)&ax,     g_ax);
    cudaGetSymbolAddress((void**)&thx,    g_thx);
    cudaGetSymbolAddress((void**)&fm,     g_fm);
    cudaGetSymbolAddress((void**)&fT,     g_fT);
    cudaGetSymbolAddress((void**)&nap,    g_nap);
    cudaGetSymbolAddress((void**)&ndp,    g_ndp);
    cudaGetSymbolAddress((void**)&nonaim, g_nonaim);
    cudaGetSymbolAddress((void**)&pooled, g_pooled);

    const long offNonDet = 0;
    const long offActDet = (long)Bc * C * Nd;
    const long offActAim = 2 * offActDet;
    const long offCw     = offActAim + (long)Bc * C * Na;

    cudaFuncSetAttribute(tgemm<0,1,4>, cudaFuncAttributeMaxDynamicSharedMemorySize, GS4);
    cudaFuncSetAttribute(tgemm<0,2,4>, cudaFuncAttributeMaxDynamicSharedMemorySize, GS4);
    cudaFuncSetAttribute(tgemm<0,0,4>, cudaFuncAttributeMaxDynamicSharedMemorySize, GS4);
    cudaFuncSetAttribute(tgemm<2,0,4>, cudaFuncAttributeMaxDynamicSharedMemorySize, GS4);
    cudaFuncSetAttribute(tgemm<0,1,2>, cudaFuncAttributeMaxDynamicSharedMemorySize, GS2);
    cudaFuncSetAttribute(tgemm<0,2,2>, cudaFuncAttributeMaxDynamicSharedMemorySize, GS2);
    cudaFuncSetAttribute(tgemm<0,0,2>, cudaFuncAttributeMaxDynamicSharedMemorySize, GS2);
    cudaFuncSetAttribute(tgemm<1,0,2>, cudaFuncAttributeMaxDynamicSharedMemorySize, GS2);

    // T0: transposes (detect/aim are [C, N]; GEMMs want K=C contiguous rows)
    transpose_k<<<dim3(Nd / 32, C / 32, Bc), dim3(32, 8)>>>(detect, detT, C, Nd);
    transpose_k<<<dim3(Na / 32, C / 32, Bc), dim3(32, 8)>>>(aim,    aimT, C, Na);

    // G1: d_x[Ci,Nd] = g_w * detT^T + g_b[m]     (WN=4, 288 CTAs)
    tgemm<0,1,4><<<dim3(Nd/256, Ci/128, Bc), 256, GS4>>>(
        g_w, detT, dx, C, Nd, 0, (long)Nd*C, (long)Ci*Nd, 1.f,
        g_b, nullptr, nullptr, nullptr, nullptr, 0, nullptr, nullptr);
    // G2: phi_x[Nd,Ci] = detT * ph_w^T + ph_b[n] (WN=4, 288)
    tgemm<0,2,4><<<dim3(Ci/256, Nd/128, Bc), 256, GS4>>>(
        detT, ph_w, phx, C, Ci, (long)Nd*C, 0, (long)Nd*Ci, 1.f,
        nullptr, ph_b, nullptr, nullptr, nullptr, 0, nullptr, nullptr);
    // G3: a_x[Ci,Na] = g_w * aimT^T + g_b[m]     (WN=2, 64)
    tgemm<0,1,2><<<dim3(Na/128, Ci/128, Bc), 128, GS2>>>(
        g_w, aimT, ax, C, Na, 0, (long)Na*C, (long)Ci*Na, 1.f,
        g_b, nullptr, nullptr, nullptr, nullptr, 0, nullptr, nullptr);
    // G4: theta_x[Na,Ci] = aimT * th_w^T + th_b[n] (WN=2, 64)
    tgemm<0,2,2><<<dim3(Ci/128, Na/128, Bc), 128, GS2>>>(
        aimT, th_w, thx, C, Ci, (long)Na*C, 0, (long)Na*Ci, 1.f,
        nullptr, th_b, nullptr, nullptr, nullptr, 0, nullptr, nullptr);
    // G5: f[Na,Nd] = theta * phi^T               (WN=2, 288)
    tgemm<0,0,2><<<dim3(Nd/128, Na/128, Bc), 128, GS2>>>(
        thx, phx, fm, Ci, Nd, (long)Na*Ci, (long)Nd*Ci, (long)Na*Nd, 1.f,
        nullptr, nullptr, nullptr, nullptr, nullptr, 0, nullptr, nullptr);
    // G5b: fT[Nd,Na] = phi * theta^T             (WN=2, 288)
    tgemm<0,0,2><<<dim3(Na/128, Nd/128, Bc), 128, GS2>>>(
        phx, thx, fT, Ci, Na, (long)Nd*Ci, (long)Na*Ci, (long)Nd*Na, 1.f,
        nullptr, nullptr, nullptr, nullptr, nullptr, 0, nullptr, nullptr);
    // G6: nap[Na,Ci] = (1/Nd) f * d_x^T          (WN=2, 64)
    tgemm<0,0,2><<<dim3(Ci/128, Na/128, Bc), 128, GS2>>>(
        fm, dx, nap, Nd, Ci, (long)Na*Nd, (long)Ci*Nd, (long)Na*Ci, 1.f/Nd,
        nullptr, nullptr, nullptr, nullptr, nullptr, 0, nullptr, nullptr);
    // G7: ndp[Nd,Ci] = (1/Na) fT * a_x^T         (WN=4, 144; K=256 short)
    tgemm<0,0,4><<<dim3(Ci/256, Nd/128, Bc), 256, GS4>>>(
        fT, ax, ndp, Na, Ci, (long)Nd*Na, (long)Ci*Na, (long)Nd*Ci, 1.f/Na,
        nullptr, nullptr, nullptr, nullptr, nullptr, 0, nullptr, nullptr);
    // G8: non_aim[C,Na] = bn(W_w * nap^T + W_b) + aim  (WN=2, 128)
    tgemm<1,0,2><<<dim3(Na/128, C/128, Bc), 128, GS2>>>(
        W_w, nap, nonaim, Ci, Na, 0, (long)Na*Ci, (long)C*Na, 1.f,
        W_b, nullptr, W_bn_g, W_bn_b, aim, (long)C*Na, nullptr, nullptr);
    // pool + gate
    pool_k<<<(Bc * C) / 8, 256>>>(nonaim, pooled);
    gate_k<<<Bc, 256>>>(pooled, m1_w, m1_b, m2_w, m2_b, out + offCw);
    // G9: non_det[C,Nd] = bn(Q_w * ndp^T + Q_b) + detect ; act_det fused (WN=4, 576)
    tgemm<2,0,4><<<dim3(Nd/256, C/128, Bc), 256, GS4>>>(
        Q_w, ndp, out + offNonDet, Ci, Nd, 0, (long)Nd*Ci, (long)C*Nd, 1.f,
        Q_b, nullptr, Q_bn_g, Q_bn_b, detect, (long)C*Nd,
        out + offCw, out + offActDet);
    // act_aim = non_aim * cw
    const long t4a = (long)Bc * C * Na / 4;
    scale_k<<<(unsigned)((t4a + 255) / 256), 256>>>(
        nonaim, out + offCw, out + offActAim, Na / 4, t4a);
}

// round 8
// speedup vs baseline: 1.1187x; 1.1187x over previous
#include <cuda_runtime.h>
#include <cstdint>
#include <math.h>

// ---------------------------------------------------------------------------
// Problem constants
// ---------------------------------------------------------------------------
constexpr int Bc = 8;
constexpr int C  = 1024;
constexpr int Ci = 512;
constexpr int Nd = 48 * 48;          // 2304
constexpr int Na = 16 * 16;          // 256
constexpr int R  = 64;               // C / 16
constexpr float BN_INV = 0.9999950000374997f;  // 1/sqrt(1+1e-5)

// ---------------------------------------------------------------------------
// Device scratch (static)
// ---------------------------------------------------------------------------
__device__ float g_detT  [Bc * Nd * C];    // rounded tf32
__device__ float g_aimT  [Bc * Na * C];    // rounded tf32
__device__ float g_dx    [Bc * Ci * Nd];
__device__ float g_phx   [Bc * Nd * Ci];
__device__ float g_ax    [Bc * Ci * Na];
__device__ float g_thx   [Bc * Na * Ci];
__device__ float g_fm    [Bc * Na * Nd];
__device__ float g_fT    [Bc * Nd * Na];
__device__ float g_nap   [Bc * Na * Ci];
__device__ float g_ndp   [Bc * Nd * Ci];
__device__ float g_nonaim[Bc * C  * Na];
__device__ float g_pooled[Bc * 2  * C];
// rounded weight copies
__device__ float g_gwr [Ci * C];
__device__ float g_thwr[Ci * C];
__device__ float g_phwr[Ci * C];
__device__ float g_Wwr [C * Ci];
__device__ float g_Qwr [C * Ci];

// ---------------------------------------------------------------------------
// helpers
// ---------------------------------------------------------------------------
__device__ __forceinline__ uint32_t f2tf(float x) {
    uint32_t r;
    asm("cvt.rna.tf32.f32 %0, %1;" : "=r"(r) : "f"(x));
    return r;
}
__device__ __forceinline__ float rnd_tf(float x) {
    return __uint_as_float(f2tf(x));
}
__device__ __forceinline__ uint32_t smem_u32(const void* p) {
    uint32_t a;
    asm("{ .reg .u64 t; cvta.to.shared.u64 t, %1; cvt.u32.u64 %0, t; }" : "=r"(a) : "l"(p));
    return a;
}
__device__ __forceinline__ void mma8(float* d, const uint32_t* a, const uint32_t* b) {
    asm volatile(
        "mma.sync.aligned.m16n8k8.row.col.f32.tf32.tf32.f32 "
        "{%0,%1,%2,%3}, {%4,%5,%6,%7}, {%8,%9}, {%0,%1,%2,%3};"
        : "+f"(d[0]), "+f"(d[1]), "+f"(d[2]), "+f"(d[3])
        : "r"(a[0]), "r"(a[1]), "r"(a[2]), "r"(a[3]), "r"(b[0]), "r"(b[1]));
}
__device__ __forceinline__ void cpa16(uint32_t s, const void* g) {
    asm volatile("cp.async.cg.shared.global [%0], [%1], 16;" :: "r"(s), "l"(g));
}
#define CPA_COMMIT() asm volatile("cp.async.commit_group;" ::: "memory")
#define CPA_WAIT2()  asm volatile("cp.async.wait_group 2;" ::: "memory")

// ---------------------------------------------------------------------------
// tf32 mma.sync GEMM:  D[M,N] = alpha * A[M,K] * B[N,K]^T  (+ epilogue)
//   Block 128x128, 8 warps (4m x 2n), warp tile 32x64, BK=16,
//   4-stage cp.async pipeline (inputs MUST already be tf32-rounded fp32;
//   cp.async truncation is then exact).
//   Smem k-stride 20 words: fragment LDS bank = 20g+t, conflict-free.
//   Requires M%128==0, N%128==0, K%16==0, row strides == K.
//   EPI 0: alpha*acc (+ bM[m] if BMODE==1, + bN[n] if BMODE==2)
//          RND=1 -> output rounded to tf32 (for GEMM-feeding intermediates)
//   EPI 1: bng[m]*BN_INV*(acc+bM[m]) + bnb[m] + resid[m*ldc+n]
//   EPI 2: EPI1 value v; additionally out2 = v * cw[bz*M + m]
// ---------------------------------------------------------------------------
constexpr int SA     = 20;                 // padded k-stride in words (16 + 4)
constexpr int AW     = 128 * SA;           // words of A per stage
constexpr int STAGEW = 256 * SA;           // words per stage (A then B)
constexpr int NSTG   = 4;
constexpr int GSMEM  = NSTG * STAGEW * 4;  // 81920 B

template<int EPI, int BMODE, int RND>
__global__ void __launch_bounds__(256, 2)
tgemm(const float* __restrict__ A, const float* __restrict__ B,
      float* __restrict__ Co,
      int K, int ldc, long strA, long strB, long strC, float alpha,
      const float* __restrict__ bM, const float* __restrict__ bN,
      const float* __restrict__ bng, const float* __restrict__ bnb,
      const float* __restrict__ resid, long sR,
      const float* __restrict__ cw, float* __restrict__ out2)
{
    extern __shared__ uint32_t sm[];
    const uint32_t smb = smem_u32(sm);

    const int tid = threadIdx.x, lane = tid & 31, wid = tid >> 5;
    const int wm = wid & 3, wn = wid >> 2;          // warp grid 4(m) x 2(n)
    const int bz = blockIdx.z;
    const int bm = blockIdx.y * 128, bn = blockIdx.x * 128;

    // loader: thread t<128 -> A row t; t>=128 -> B row t-128; 64 B each (BK=16)
    const int lrow = tid & 127;
    const bool isA = tid < 128;
    const float* gbase = isA
        ? A + (long)bz * strA + (long)(bm + lrow) * K
        : B + (long)bz * strB + (long)(bn + lrow) * K;
    const uint32_t sbase = smb + (uint32_t)(((isA ? 0 : AW) + lrow * SA) * 4);

    auto loadt = [&](int kt, int st) {
        const float* gp = gbase + kt * 16;
        const uint32_t sp = sbase + (uint32_t)(st * STAGEW * 4);
        #pragma unroll
        for (int j = 0; j < 4; j++) cpa16(sp + j * 16, gp + j * 4);
    };

    float acc[2][8][4];
    #pragma unroll
    for (int i = 0; i < 2; i++)
        #pragma unroll
        for (int j = 0; j < 8; j++)
            #pragma unroll
            for (int q = 0; q < 4; q++) acc[i][j][q] = 0.f;

    const int g = lane >> 2, t = lane & 3;
    auto compute = [&](int st) {
        const uint32_t* asb = sm + st * STAGEW;
        const uint32_t* bsb = asb + AW;
        #pragma unroll
        for (int k8 = 0; k8 < 2; k8++) {
            const int kb = k8 * 8;
            uint32_t af[2][4];
            #pragma unroll
            for (int mi = 0; mi < 2; mi++) {
                const uint32_t* p = asb + (wm * 32 + mi * 16 + g) * SA + kb + t;
                af[mi][0] = p[0];
                af[mi][1] = p[8 * SA];
                af[mi][2] = p[4];
                af[mi][3] = p[8 * SA + 4];
            }
            #pragma unroll
            for (int ni = 0; ni < 8; ni++) {
                const uint32_t* p = bsb + (wn * 64 + ni * 8 + g) * SA + kb + t;
                uint32_t bf[2] = { p[0], p[4] };
                mma8(acc[0][ni], af[0], bf);
                mma8(acc[1][ni], af[1], bf);
            }
        }
    };

    const int nk = K / 16;          // >= 16 for all GEMMs here
    loadt(0, 0); CPA_COMMIT();
    loadt(1, 1); CPA_COMMIT();
    loadt(2, 2); CPA_COMMIT();

    for (int kt = 0; kt < nk; kt++) {
        const int s = kt & 3;
        CPA_WAIT2();                 // own group kt complete (one commit/iter)
        __syncthreads();             // everyone's writes visible; prev compute done
        if (kt + 3 < nk) loadt(kt + 3, (kt + 3) & 3);
        CPA_COMMIT();                // commit every iter (possibly empty group)
        compute(s);
    }

    // ---- epilogue ----
    const int t2 = (lane & 3) * 2;
    #pragma unroll
    for (int mi = 0; mi < 2; mi++) {
        #pragma unroll
        for (int half = 0; half < 2; half++) {
            const int m = bm + wm * 32 + mi * 16 + half * 8 + g;
            float addM = 0.f, sc = 1.f, be = 0.f, gwv = 0.f;
            if constexpr (EPI == 0) {
                if constexpr (BMODE == 1) addM = bM[m];
            } else {
                addM = bM[m]; sc = bng[m] * BN_INV; be = bnb[m];
            }
            float* crow = Co + (long)bz * strC + (long)m * ldc;
            const float* rrow = nullptr;
            float* o2row = nullptr;
            if constexpr (EPI >= 1) rrow = resid + (long)bz * sR + (long)m * ldc;
            if constexpr (EPI == 2) {
                o2row = out2 + (long)bz * strC + (long)m * ldc;
                gwv = cw[(long)bz * (gridDim.y * 128) + m];
            }
            #pragma unroll
            for (int ni = 0; ni < 8; ni++) {
                const int n = bn + wn * 64 + ni * 8 + t2;
                const float c0 = acc[mi][ni][half * 2 + 0];
                const float c1 = acc[mi][ni][half * 2 + 1];
                float2 o;
                if constexpr (EPI == 0) {
                    o.x = alpha * c0 + addM;
                    o.y = alpha * c1 + addM;
                    if constexpr (BMODE == 2) { o.x += bN[n]; o.y += bN[n + 1]; }
                    if constexpr (RND == 1) { o.x = rnd_tf(o.x); o.y = rnd_tf(o.y); }
                } else {
                    float2 rv = *(const float2*)&rrow[n];
                    o.x = sc * (c0 + addM) + be + rv.x;
                    o.y = sc * (c1 + addM) + be + rv.y;
                }
                *(float2*)&crow[n] = o;
                if constexpr (EPI == 2) {
                    float2 o2 = { o.x * gwv, o.y * gwv };
                    *(float2*)&o2row[n] = o2;
                }
            }
        }
    }
}

// ---------------------------------------------------------------------------
// Weight rounding: dst = tf32(src), float4-vectorized
// ---------------------------------------------------------------------------
__global__ void round_k(const float* __restrict__ src, float* __restrict__ dst, int n4)
{
    const int i = blockIdx.x * blockDim.x + threadIdx.x;
    if (i >= n4) return;
    float4 v = ((const float4*)src)[i];
    v.x = rnd_tf(v.x); v.y = rnd_tf(v.y); v.z = rnd_tf(v.z); v.w = rnd_tf(v.w);
    ((float4*)dst)[i] = v;
}

// ---------------------------------------------------------------------------
// Transpose + tf32 round: src [rows][cols] -> dst [cols][rows], per batch z
// ---------------------------------------------------------------------------
__global__ void transpose_k(const float* __restrict__ src, float* __restrict__ dst,
                            int rows, int cols)
{
    __shared__ float t[32][33];
    const long bo = (long)blockIdx.z * rows * cols;
    const int c0 = blockIdx.x * 32, r0 = blockIdx.y * 32;
    const int tx = threadIdx.x, ty = threadIdx.y;
    #pragma unroll
    for (int i = 0; i < 32; i += 8)
        t[ty + i][tx] = rnd_tf(src[bo + (long)(r0 + ty + i) * cols + c0 + tx]);
    __syncthreads();
    #pragma unroll
    for (int i = 0; i < 32; i += 8)
        dst[bo + (long)(c0 + ty + i) * rows + r0 + tx] = t[tx][ty + i];
}

// ---------------------------------------------------------------------------
// Avg+Max pooling: one warp per (b,c)
// ---------------------------------------------------------------------------
__global__ void pool_k(const float* __restrict__ na, float* __restrict__ pooled)
{
    const int gw = (int)((blockIdx.x * (long)blockDim.x + threadIdx.x) >> 5);
    const int lane = threadIdx.x & 31;
    if (gw >= Bc * C) return;
    const float* p = na + (long)gw * Na;
    float s = 0.f, m = -3.4e38f;
    for (int i = lane; i < Na; i += 32) { float v = p[i]; s += v; m = fmaxf(m, v); }
    #pragma unroll
    for (int o = 16; o; o >>= 1) {
        s += __shfl_xor_sync(0xffffffffu, s, o);
        m = fmaxf(m, __shfl_xor_sync(0xffffffffu, m, o));
    }
    if (lane == 0) {
        const int b = gw / C, c = gw % C;
        pooled[(long)b * 2 * C + c]     = s * (1.f / Na);
        pooled[(long)b * 2 * C + C + c] = m;
    }
}

// ---------------------------------------------------------------------------
// Channel gate MLP + sigmoid, one block per batch
// ---------------------------------------------------------------------------
__global__ void gate_k(const float* __restrict__ pooled,
                       const float* __restrict__ w1, const float* __restrict__ b1,
                       const float* __restrict__ w2, const float* __restrict__ b2,
                       float* __restrict__ cw)
{
    __shared__ float sv[2 * C];
    __shared__ float h[2][R];
    __shared__ float hs[R];
    const int b = blockIdx.x, tid = threadIdx.x;
    for (int i = tid; i < 2 * C; i += blockDim.x)
        sv[i] = pooled[(long)b * 2 * C + i];
    __syncthreads();
    if (tid < 2 * R) {
        const int which = tid / R, r = tid % R;
        const float* v = sv + which * C;
        const float* wr = w1 + r * C;
        float acc = b1[r];
        for (int c = 0; c < C; c++) acc += wr[c] * v[c];
        h[which][r] = fmaxf(acc, 0.f);
    }
    __syncthreads();
    if (tid < R) hs[tid] = h[0][tid] + h[1][tid];
    __syncthreads();
    for (int c = tid; c < C; c += blockDim.x) {
        const float* wc = w2 + c * R;
        float acc = 2.f * b2[c];
        #pragma unroll 8
        for (int r = 0; r < R; r++) acc += wc[r] * hs[r];
        cw[(long)b * C + c] = 1.f / (1.f + expf(-acc));
    }
}

// ---------------------------------------------------------------------------
// Channel scaling (act_aim): dst = src * cw[b*C + c]
// ---------------------------------------------------------------------------
__global__ void scale_k(const float* __restrict__ src, const float* __restrict__ cw,
                        float* __restrict__ dst, int q_div, long total4)
{
    const long i = blockIdx.x * (long)blockDim.x + threadIdx.x;
    if (i >= total4) return;
    const float w = cw[i / q_div];
    float4 v = ((const float4*)src)[i];
    v.x *= w; v.y *= w; v.z *= w; v.w *= w;
    ((float4*)dst)[i] = v;
}

// ---------------------------------------------------------------------------
// Launch
// ---------------------------------------------------------------------------
extern "C" void kernel_launch(void* const* d_in, const int* in_sizes, int n_in,
                              void* d_out, int out_size)
{
    (void)in_sizes; (void)n_in; (void)out_size;
    const float* detect = (const float*)d_in[0];
    const float* aim    = (const float*)d_in[1];
    const float* g_w    = (const float*)d_in[2];
    const float* g_b    = (const float*)d_in[3];
    const float* th_w   = (const float*)d_in[4];
    const float* th_b   = (const float*)d_in[5];
    const float* ph_w   = (const float*)d_in[6];
    const float* ph_b   = (const float*)d_in[7];
    const float* W_w    = (const float*)d_in[8];
    const float* W_b    = (const float*)d_in[9];
    const float* W_bn_g = (const float*)d_in[10];
    const float* W_bn_b = (const float*)d_in[11];
    const float* Q_w    = (const float*)d_in[12];
    const float* Q_b    = (const float*)d_in[13];
    const float* Q_bn_g = (const float*)d_in[14];
    const float* Q_bn_b = (const float*)d_in[15];
    const float* m1_w   = (const float*)d_in[16];
    const float* m1_b   = (const float*)d_in[17];
    const float* m2_w   = (const float*)d_in[18];
    const float* m2_b   = (const float*)d_in[19];
    float* out = (float*)d_out;

    float *detT, *aimT, *dx, *phx, *ax, *thx, *fm, *fT, *nap, *ndp, *nonaim, *pooled;
    float *gwr, *thwr, *phwr, *Wwr, *Qwr;
    cudaGetSymbolAddress((void**)&detT,   g_detT);
    cudaGetSymbolAddress((void**)&aimT,   g_aimT);
    cudaGetSymbolAddress((void**)&dx,     g_dx);
    cudaGetSymbolAddress((void**)&phx,    g_phx);
    cudaGetSymbolAddress((void**)&ax,     g_ax);
    cudaGetSymbolAddress((void**)&thx,    g_thx);
    cudaGetSymbolAddress((void**)&fm,     g_fm);
    cudaGetSymbolAddress((void**)&fT,     g_fT);
    cudaGetSymbolAddress((void**)&nap,    g_nap);
    cudaGetSymbolAddress((void**)&ndp,    g_ndp);
    cudaGetSymbolAddress((void**)&nonaim, g_nonaim);
    cudaGetSymbolAddress((void**)&pooled, g_pooled);
    cudaGetSymbolAddress((void**)&gwr,    g_gwr);
    cudaGetSymbolAddress((void**)&thwr,   g_thwr);
    cudaGetSymbolAddress((void**)&phwr,   g_phwr);
    cudaGetSymbolAddress((void**)&Wwr,    g_Wwr);
    cudaGetSymbolAddress((void**)&Qwr,    g_Qwr);

    const long offNonDet = 0;
    const long offActDet = (long)Bc * C * Nd;
    const long offActAim = 2 * offActDet;
    const long offCw     = offActAim + (long)Bc * C * Na;

    cudaFuncSetAttribute(tgemm<0,0,1>, cudaFuncAttributeMaxDynamicSharedMemorySize, GSMEM);
    cudaFuncSetAttribute(tgemm<0,1,1>, cudaFuncAttributeMaxDynamicSharedMemorySize, GSMEM);
    cudaFuncSetAttribute(tgemm<0,2,1>, cudaFuncAttributeMaxDynamicSharedMemorySize, GSMEM);
    cudaFuncSetAttribute(tgemm<1,0,0>, cudaFuncAttributeMaxDynamicSharedMemorySize, GSMEM);
    cudaFuncSetAttribute(tgemm<2,0,0>, cudaFuncAttributeMaxDynamicSharedMemorySize, GSMEM);

    // T0: transpose + round activations; round weights
    transpose_k<<<dim3(Nd / 32, C / 32, Bc), dim3(32, 8)>>>(detect, detT, C, Nd);
    transpose_k<<<dim3(Na / 32, C / 32, Bc), dim3(32, 8)>>>(aim,    aimT, C, Na);
    {
        const int n4 = (Ci * C) / 4;   // all five weight mats are Ci*C elements
        round_k<<<(n4 + 255) / 256, 256>>>(g_w,  gwr,  n4);
        round_k<<<(n4 + 255) / 256, 256>>>(th_w, thwr, n4);
        round_k<<<(n4 + 255) / 256, 256>>>(ph_w, phwr, n4);
        round_k<<<(n4 + 255) / 256, 256>>>(W_w,  Wwr,  n4);
        round_k<<<(n4 + 255) / 256, 256>>>(Q_w,  Qwr,  n4);
    }

    // G1: d_x[Ci,Nd] = gwr * detT^T + g_b[m]          (rounded out)
    tgemm<0,1,1><<<dim3(Nd/128, Ci/128, Bc), 256, GSMEM>>>(
        gwr, detT, dx, C, Nd, 0, (long)Nd*C, (long)Ci*Nd, 1.f,
        g_b, nullptr, nullptr, nullptr, nullptr, 0, nullptr, nullptr);
    // G2: phi_x[Nd,Ci] = detT * phwr^T + ph_b[n]      (rounded out)
    tgemm<0,2,1><<<dim3(Ci/128, Nd/128, Bc), 256, GSMEM>>>(
        detT, phwr, phx, C, Ci, (long)Nd*C, 0, (long)Nd*Ci, 1.f,
        nullptr, ph_b, nullptr, nullptr, nullptr, 0, nullptr, nullptr);
    // G3: a_x[Ci,Na] = gwr * aimT^T + g_b[m]          (rounded out)
    tgemm<0,1,1><<<dim3(Na/128, Ci/128, Bc), 256, GSMEM>>>(
        gwr, aimT, ax, C, Na, 0, (long)Na*C, (long)Ci*Na, 1.f,
        g_b, nullptr, nullptr, nullptr, nullptr, 0, nullptr, nullptr);
    // G4: theta_x[Na,Ci] = aimT * thwr^T + th_b[n]    (rounded out)
    tgemm<0,2,1><<<dim3(Ci/128, Na/128, Bc), 256, GSMEM>>>(
        aimT, thwr, thx, C, Ci, (long)Na*C, 0, (long)Na*Ci, 1.f,
        nullptr, th_b, nullptr, nullptr, nullptr, 0, nullptr, nullptr);
    // G5: f[Na,Nd] = theta * phi^T                    (rounded out)
    tgemm<0,0,1><<<dim3(Nd/128, Na/128, Bc), 256, GSMEM>>>(
        thx, phx, fm, Ci, Nd, (long)Na*Ci, (long)Nd*Ci, (long)Na*Nd, 1.f,
        nullptr, nullptr, nullptr, nullptr, nullptr, 0, nullptr, nullptr);
    // G5b: fT[Nd,Na] = phi * theta^T                  (rounded out)
    tgemm<0,0,1><<<dim3(Na/128, Nd/128, Bc), 256, GSMEM>>>(
        phx, thx, fT, Ci, Na, (long)Nd*Ci, (long)Na*Ci, (long)Nd*Na, 1.f,
        nullptr, nullptr, nullptr, nullptr, nullptr, 0, nullptr, nullptr);
    // G6: nap[Na,Ci] = (1/Nd) f * d_x^T               (rounded out)
    tgemm<0,0,1><<<dim3(Ci/128, Na/128, Bc), 256, GSMEM>>>(
        fm, dx, nap, Nd, Ci, (long)Na*Nd, (long)Ci*Nd, (long)Na*Ci, 1.f/Nd,
        nullptr, nullptr, nullptr, nullptr, nullptr, 0, nullptr, nullptr);
    // G7: ndp[Nd,Ci] = (1/Na) fT * a_x^T              (rounded out)
    tgemm<0,0,1><<<dim3(Ci/128, Nd/128, Bc), 256, GSMEM>>>(
        fT, ax, ndp, Na, Ci, (long)Nd*Na, (long)Ci*Na, (long)Nd*Ci, 1.f/Na,
        nullptr, nullptr, nullptr, nullptr, nullptr, 0, nullptr, nullptr);
    // G8: non_aim[C,Na] = bn(Wwr * nap^T + W_b) + aim (full precision out)
    tgemm<1,0,0><<<dim3(Na/128, C/128, Bc), 256, GSMEM>>>(
        Wwr, nap, nonaim, Ci, Na, 0, (long)Na*Ci, (long)C*Na, 1.f,
        W_b, nullptr, W_bn_g, W_bn_b, aim, (long)C*Na, nullptr, nullptr);
    // pool + gate
    pool_k<<<(Bc * C) / 8, 256>>>(nonaim, pooled);
    gate_k<<<Bc, 256>>>(pooled, m1_w, m1_b, m2_w, m2_b, out + offCw);
    // G9: non_det[C,Nd] = bn(Qwr * ndp^T + Q_b) + detect ; act_det fused
    tgemm<2,0,0><<<dim3(Nd/128, C/128, Bc), 256, GSMEM>>>(
        Qwr, ndp, out + offNonDet, Ci, Nd, 0, (long)Nd*Ci, (long)C*Nd, 1.f,
        Q_b, nullptr, Q_bn_g, Q_bn_b, detect, (long)C*Nd,
        out + offCw, out + offActDet);
    // act_aim = non_aim * cw
    const long t4a = (long)Bc * C * Na / 4;
    scale_k<<<(unsigned)((t4a + 255) / 256), 256>>>(
        nonaim, out + offCw, out + offActAim, Na / 4, t4a);
}

// round 10
// speedup vs baseline: 1.2701x; 1.1354x over previous
#include <cuda_runtime.h>
#include <cstdint>
#include <math.h>

// ---------------------------------------------------------------------------
// Problem constants
// ---------------------------------------------------------------------------
constexpr int Bc = 8;
constexpr int C  = 1024;
constexpr int Ci = 512;
constexpr int Nd = 48 * 48;          // 2304
constexpr int Na = 16 * 16;          // 256
constexpr int R  = 64;               // C / 16
constexpr float BN_INV = 0.9999950000374997f;  // 1/sqrt(1+1e-5)

// ---------------------------------------------------------------------------
// Device scratch (static)
// ---------------------------------------------------------------------------
__device__ float g_detT  [Bc * Nd * C];    // rounded tf32
__device__ float g_aimT  [Bc * Na * C];    // rounded tf32
__device__ float g_dx    [Bc * Ci * Nd];
__device__ float g_phx   [Bc * Nd * Ci];
__device__ float g_ax    [Bc * Ci * Na];
__device__ float g_thx   [Bc * Na * Ci];
__device__ float g_fm    [Bc * Na * Nd];
__device__ float g_fT    [Bc * Nd * Na];
__device__ float g_nap   [Bc * Na * Ci];
__device__ float g_ndp   [Bc * Nd * Ci];
__device__ float g_nonaim[Bc * C  * Na];
__device__ float g_pooled[Bc * 2  * C];
// rounded weight copies
__device__ float g_gwr [Ci * C];
__device__ float g_thwr[Ci * C];
__device__ float g_phwr[Ci * C];
__device__ float g_Wwr [C * Ci];
__device__ float g_Qwr [C * Ci];

// ---------------------------------------------------------------------------
// helpers
// ---------------------------------------------------------------------------
__device__ __forceinline__ uint32_t f2tf(float x) {
    uint32_t r;
    asm("cvt.rna.tf32.f32 %0, %1;" : "=r"(r) : "f"(x));
    return r;
}
__device__ __forceinline__ float rnd_tf(float x) {
    return __uint_as_float(f2tf(x));
}
__device__ __forceinline__ uint32_t smem_u32(const void* p) {
    uint32_t a;
    asm("{ .reg .u64 t; cvta.to.shared.u64 t, %1; cvt.u32.u64 %0, t; }" : "=r"(a) : "l"(p));
    return a;
}
__device__ __forceinline__ void mma8(float* d, const uint32_t* a, const uint32_t* b) {
    asm volatile(
        "mma.sync.aligned.m16n8k8.row.col.f32.tf32.tf32.f32 "
        "{%0,%1,%2,%3}, {%4,%5,%6,%7}, {%8,%9}, {%0,%1,%2,%3};"
        : "+f"(d[0]), "+f"(d[1]), "+f"(d[2]), "+f"(d[3])
        : "r"(a[0]), "r"(a[1]), "r"(a[2]), "r"(a[3]), "r"(b[0]), "r"(b[1]));
}
__device__ __forceinline__ void ldsm4(uint32_t* r, uint32_t a) {
    asm volatile("ldmatrix.sync.aligned.m8n8.x4.shared.b16 {%0,%1,%2,%3}, [%4];"
        : "=r"(r[0]), "=r"(r[1]), "=r"(r[2]), "=r"(r[3]) : "r"(a));
}
__device__ __forceinline__ void cpa16(uint32_t s, const void* g) {
    asm volatile("cp.async.cg.shared.global [%0], [%1], 16;" :: "r"(s), "l"(g));
}
#define CPA_COMMIT() asm volatile("cp.async.commit_group;" ::: "memory")
#define CPA_WAIT2()  asm volatile("cp.async.wait_group 2;" ::: "memory")

// ---------------------------------------------------------------------------
// tf32 mma.sync GEMM:  D[M,N] = alpha * A[M,K] * B[N,K]^T  (+ epilogue)
//   Block 128x128, 8 warps (4m x 2n), warp tile 32x64, BK=16, 4-stage
//   cp.async pipeline. Fragment loads via ldmatrix.x4:
//     A: 2 ldmatrix/warp/k8 (was 8 scalar LDS) -> a0..a3 fragments
//     B: 4 ldmatrix/warp/k8 (was 16 scalar LDS) -> b0,b1 for 8 ni tiles
//   m8n8.b16 on tf32 data: 8 rows x 16B rows, lane l <- word l%4 of row l/4,
//   exactly the m16n8k8 fragment layout (g = lane>>2, t = lane&3).
//   Inputs MUST be tf32-pre-rounded fp32 (cp.async truncation then exact).
//   Smem k-stride 20 words: each ldmatrix phase (8 rows stride 20, 4-word
//   runs at +{0,20,8,28,16,4,24,12} mod 32) covers all banks once.
//   All row addresses 16B-aligned ((row*20 + {0,4})*4 mod 16 == 0).
//   Requires M%128==0, N%128==0, K%16==0, row strides == K.
//   EPI 0: alpha*acc (+ bM[m] if BMODE==1, + bN[n] if BMODE==2)
//          RND=1 -> output rounded to tf32 (GEMM-feeding intermediates)
//   EPI 1: bng[m]*BN_INV*(acc+bM[m]) + bnb[m] + resid[m*ldc+n]
//   EPI 2: EPI1 value v; additionally out2 = v * cw[bz*M + m]
// ---------------------------------------------------------------------------
constexpr int SA     = 20;                 // padded k-stride in words (16 + 4)
constexpr int AW     = 128 * SA;           // words of A per stage
constexpr int STAGEW = 256 * SA;           // words per stage (A then B)
constexpr int STAGEB = STAGEW * 4;         // bytes per stage
constexpr int NSTG   = 4;
constexpr int GSMEM  = NSTG * STAGEB;      // 81920 B

template<int EPI, int BMODE, int RND>
__global__ void __launch_bounds__(256, 2)
tgemm(const float* __restrict__ A, const float* __restrict__ B,
      float* __restrict__ Co,
      int K, int ldc, long strA, long strB, long strC, float alpha,
      const float* __restrict__ bM, const float* __restrict__ bN,
      const float* __restrict__ bng, const float* __restrict__ bnb,
      const float* __restrict__ resid, long sR,
      const float* __restrict__ cw, float* __restrict__ out2)
{
    extern __shared__ uint32_t sm[];
    const uint32_t smb = smem_u32(sm);

    const int tid = threadIdx.x, lane = tid & 31, wid = tid >> 5;
    const int wm = wid & 3, wn = wid >> 2;          // warp grid 4(m) x 2(n)
    const int bz = blockIdx.z;
    const int bm = blockIdx.y * 128, bn = blockIdx.x * 128;

    // loader: thread t<128 -> A row t; t>=128 -> B row t-128; 64 B each (BK=16)
    const int lrow = tid & 127;
    const bool isA = tid < 128;
    const float* gbase = isA
        ? A + (long)bz * strA + (long)(bm + lrow) * K
        : B + (long)bz * strB + (long)(bn + lrow) * K;
    const uint32_t sbase = smb + (uint32_t)(((isA ? 0 : AW) + lrow * SA) * 4);

    auto loadt = [&](int kt, int st) {
        const float* gp = gbase + kt * 16;
        const uint32_t sp = sbase + (uint32_t)(st * STAGEB);
        #pragma unroll
        for (int j = 0; j < 4; j++) cpa16(sp + j * 16, gp + j * 4);
    };

    // ldmatrix per-thread base addresses (stage 0, k8 = 0):
    // A: matrix0 = rows wm*32+0..7 @kb, m1 = rows +8..15 @kb,
    //    m2 = rows 0..7 @kb+4, m3 = rows 8..15 @kb+4  -> af = {a0,a1,a2,a3}
    //    lane addr: row = wm*32 + (lane & 15), colw = 4*(lane >> 4)
    // B: for ni pair p (rows wn*64 + p*16 + 0..15):
    //    m0 = rows 0..7 @kb (b0 of ni=2p), m1 = rows 0..7 @kb+4 (b1 of 2p),
    //    m2 = rows 8..15 @kb (b0 of 2p+1), m3 = rows 8..15 @kb+4 (b1 of 2p+1)
    //    lane addr: row = wn*64 + (lane & 7) + 8*(lane >> 4),
    //               colw = 4*((lane >> 3) & 1)
    const uint32_t aAddr = smb +
        (uint32_t)(((wm * 32 + (lane & 15)) * SA + 4 * (lane >> 4)) * 4);
    const uint32_t bAddr = smb +
        (uint32_t)((AW + (wn * 64 + (lane & 7) + 8 * (lane >> 4)) * SA
                    + 4 * ((lane >> 3) & 1)) * 4);

    float acc[2][8][4];
    #pragma unroll
    for (int i = 0; i < 2; i++)
        #pragma unroll
        for (int j = 0; j < 8; j++)
            #pragma unroll
            for (int q = 0; q < 4; q++) acc[i][j][q] = 0.f;

    auto compute = [&](int st) {
        const uint32_t stoff = (uint32_t)(st * STAGEB);
        #pragma unroll
        for (int k8 = 0; k8 < 2; k8++) {
            const uint32_t kboff = stoff + (uint32_t)(k8 * 32);   // 8 words
            uint32_t af[2][4];
            ldsm4(af[0], aAddr + kboff);
            ldsm4(af[1], aAddr + kboff + 16 * SA * 4);
            uint32_t bf[4][4];
            #pragma unroll
            for (int p = 0; p < 4; p++)
                ldsm4(bf[p], bAddr + kboff + (uint32_t)(p * 16 * SA * 4));
            #pragma unroll
            for (int ni = 0; ni < 8; ni++) {
                const uint32_t* bb = &bf[ni >> 1][(ni & 1) * 2];
                mma8(acc[0][ni], af[0], bb);
                mma8(acc[1][ni], af[1], bb);
            }
        }
    };

    const int nk = K / 16;          // >= 16 for all GEMMs here
    loadt(0, 0); CPA_COMMIT();
    loadt(1, 1); CPA_COMMIT();
    loadt(2, 2); CPA_COMMIT();

    for (int kt = 0; kt < nk; kt++) {
        const int s = kt & 3;
        CPA_WAIT2();                 // own group kt complete (one commit/iter)
        __syncthreads();             // writes visible; prev compute done
        if (kt + 3 < nk) loadt(kt + 3, (kt + 3) & 3);
        CPA_COMMIT();                // commit every iter (possibly empty)
        compute(s);
    }

    // ---- epilogue ----
    const int g = lane >> 2, t2 = (lane & 3) * 2;
    #pragma unroll
    for (int mi = 0; mi < 2; mi++) {
        #pragma unroll
        for (int half = 0; half < 2; half++) {
            const int m = bm + wm * 32 + mi * 16 + half * 8 + g;
            float addM = 0.f, sc = 1.f, be = 0.f, gwv = 0.f;
            if constexpr (EPI == 0) {
                if constexpr (BMODE == 1) addM = bM[m];
            } else {
                addM = bM[m]; sc = bng[m] * BN_INV; be = bnb[m];
            }
            float* crow = Co + (long)bz * strC + (long)m * ldc;
            const float* rrow = nullptr;
            float* o2row = nullptr;
            if constexpr (EPI >= 1) rrow = resid + (long)bz * sR + (long)m * ldc;
            if constexpr (EPI == 2) {
                o2row = out2 + (long)bz * strC + (long)m * ldc;
                gwv = cw[(long)bz * (gridDim.y * 128) + m];
            }
            #pragma unroll
            for (int ni = 0; ni < 8; ni++) {
                const int n = bn + wn * 64 + ni * 8 + t2;
                const float c0 = acc[mi][ni][half * 2 + 0];
                const float c1 = acc[mi][ni][half * 2 + 1];
                float2 o;
                if constexpr (EPI == 0) {
                    o.x = alpha * c0 + addM;
                    o.y = alpha * c1 + addM;
                    if constexpr (BMODE == 2) { o.x += bN[n]; o.y += bN[n + 1]; }
                    if constexpr (RND == 1) { o.x = rnd_tf(o.x); o.y = rnd_tf(o.y); }
                } else {
                    float2 rv = *(const float2*)&rrow[n];
                    o.x = sc * (c0 + addM) + be + rv.x;
                    o.y = sc * (c1 + addM) + be + rv.y;
                }
                *(float2*)&crow[n] = o;
                if constexpr (EPI == 2) {
                    float2 o2 = { o.x * gwv, o.y * gwv };
                    *(float2*)&o2row[n] = o2;
                }
            }
        }
    }
}

// ---------------------------------------------------------------------------
// Weight rounding: dst = tf32(src), float4-vectorized
// ---------------------------------------------------------------------------
__global__ void round_k(const float* __restrict__ src, float* __restrict__ dst, int n4)
{
    const int i = blockIdx.x * blockDim.x + threadIdx.x;
    if (i >= n4) return;
    float4 v = ((const float4*)src)[i];
    v.x = rnd_tf(v.x); v.y = rnd_tf(v.y); v.z = rnd_tf(v.z); v.w = rnd_tf(v.w);
    ((float4*)dst)[i] = v;
}

// ---------------------------------------------------------------------------
// Transpose + tf32 round: src [rows][cols] -> dst [cols][rows], per batch z
// ---------------------------------------------------------------------------
__global__ void transpose_k(const float* __restrict__ src, float* __restrict__ dst,
                            int rows, int cols)
{
    __shared__ float t[32][33];
    const long bo = (long)blockIdx.z * rows * cols;
    const int c0 = blockIdx.x * 32, r0 = blockIdx.y * 32;
    const int tx = threadIdx.x, ty = threadIdx.y;
    #pragma unroll
    for (int i = 0; i < 32; i += 8)
        t[ty + i][tx] = rnd_tf(src[bo + (long)(r0 + ty + i) * cols + c0 + tx]);
    __syncthreads();
    #pragma unroll
    for (int i = 0; i < 32; i += 8)
        dst[bo + (long)(c0 + ty + i) * rows + r0 + tx] = t[tx][ty + i];
}

// ---------------------------------------------------------------------------
// Avg+Max pooling: one warp per (b,c)
// ---------------------------------------------------------------------------
__global__ void pool_k(const float* __restrict__ na, float* __restrict__ pooled)
{
    const int gw = (int)((blockIdx.x * (long)blockDim.x + threadIdx.x) >> 5);
    const int lane = threadIdx.x & 31;
    if (gw >= Bc * C) return;
    const float* p = na + (long)gw * Na;
    float s = 0.f, m = -3.4e38f;
    for (int i = lane; i < Na; i += 32) { float v = p[i]; s += v; m = fmaxf(m, v); }
    #pragma unroll
    for (int o = 16; o; o >>= 1) {
        s += __shfl_xor_sync(0xffffffffu, s, o);
        m = fmaxf(m, __shfl_xor_sync(0xffffffffu, m, o));
    }
    if (lane == 0) {
        const int b = gw / C, c = gw % C;
        pooled[(long)b * 2 * C + c]     = s * (1.f / Na);
        pooled[(long)b * 2 * C + C + c] = m;
    }
}

// ---------------------------------------------------------------------------
// Channel gate MLP + sigmoid, one block per batch
// ---------------------------------------------------------------------------
__global__ void gate_k(const float* __restrict__ pooled,
                       const float* __restrict__ w1, const float* __restrict__ b1,
                       const float* __restrict__ w2, const float* __restrict__ b2,
                       float* __restrict__ cw)
{
    __shared__ float sv[2 * C];
    __shared__ float h[2][R];
    __shared__ float hs[R];
    const int b = blockIdx.x, tid = threadIdx.x;
    for (int i = tid; i < 2 * C; i += blockDim.x)
        sv[i] = pooled[(long)b * 2 * C + i];
    __syncthreads();
    if (tid < 2 * R) {
        const int which = tid / R, r = tid % R;
        const float* v = sv + which * C;
        const float* wr = w1 + r * C;
        float acc = b1[r];
        for (int c = 0; c < C; c++) acc += wr[c] * v[c];
        h[which][r] = fmaxf(acc, 0.f);
    }
    __syncthreads();
    if (tid < R) hs[tid] = h[0][tid] + h[1][tid];
    __syncthreads();
    for (int c = tid; c < C; c += blockDim.x) {
        const float* wc = w2 + c * R;
        float acc = 2.f * b2[c];
        #pragma unroll 8
        for (int r = 0; r < R; r++) acc += wc[r] * hs[r];
        cw[(long)b * C + c] = 1.f / (1.f + expf(-acc));
    }
}

// ---------------------------------------------------------------------------
// Channel scaling (act_aim): dst = src * cw[b*C + c]
// ---------------------------------------------------------------------------
__global__ void scale_k(const float* __restrict__ src, const float* __restrict__ cw,
                        float* __restrict__ dst, int q_div, long total4)
{
    const long i = blockIdx.x * (long)blockDim.x + threadIdx.x;
    if (i >= total4) return;
    const float w = cw[i / q_div];
    float4 v = ((const float4*)src)[i];
    v.x *= w; v.y *= w; v.z *= w; v.w *= w;
    ((float4*)dst)[i] = v;
}

// ---------------------------------------------------------------------------
// Launch
// ---------------------------------------------------------------------------
extern "C" void kernel_launch(void* const* d_in, const int* in_sizes, int n_in,
                              void* d_out, int out_size)
{
    (void)in_sizes; (void)n_in; (void)out_size;
    const float* detect = (const float*)d_in[0];
    const float* aim    = (const float*)d_in[1];
    const float* g_w    = (const float*)d_in[2];
    const float* g_b    = (const float*)d_in[3];
    const float* th_w   = (const float*)d_in[4];
    const float* th_b   = (const float*)d_in[5];
    const float* ph_w   = (const float*)d_in[6];
    const float* ph_b   = (const float*)d_in[7];
    const float* W_w    = (const float*)d_in[8];
    const float* W_b    = (const float*)d_in[9];
    const float* W_bn_g = (const float*)d_in[10];
    const float* W_bn_b = (const float*)d_in[11];
    const float* Q_w    = (const float*)d_in[12];
    const float* Q_b    = (const float*)d_in[13];
    const float* Q_bn_g = (const float*)d_in[14];
    const float* Q_bn_b = (const float*)d_in[15];
    const float* m1_w   = (const float*)d_in[16];
    const float* m1_b   = (const float*)d_in[17];
    const float* m2_w   = (const float*)d_in[18];
    const float* m2_b   = (const float*)d_in[19];
    float* out = (float*)d_out;

    float *detT, *aimT, *dx, *phx, *ax, *thx, *fm, *fT, *nap, *ndp, *nonaim, *pooled;
    float *gwr, *thwr, *phwr, *Wwr, *Qwr;
    cudaGetSymbolAddress((void**)&detT,   g_detT);
    cudaGetSymbolAddress((void**)&aimT,   g_aimT);
    cudaGetSymbolAddress((void**)&dx,     g_dx);
    cudaGetSymbolAddress((void**)&phx,    g_phx);
    cudaGetSymbolAddress((void**)&ax,     g_ax);
    cudaGetSymbolAddress((void**)&thx,    g_thx);
    cudaGetSymbolAddress((void**)&fm,     g_fm);
    cudaGetSymbolAddress((void**)&fT,     g_fT);
    cudaGetSymbolAddress((void**)&nap,    g_nap);
    cudaGetSymbolAddress((void**)&ndp,    g_ndp);
    cudaGetSymbolAddress((void**)&nonaim, g_nonaim);
    cudaGetSymbolAddress((void**)&pooled, g_pooled);
    cudaGetSymbolAddress((void**)&gwr,    g_gwr);
    cudaGetSymbolAddress((void**)&thwr,   g_thwr);
    cudaGetSymbolAddress((void**)&phwr,   g_phwr);
    cudaGetSymbolAddress((void**)&Wwr,    g_Wwr);
    cudaGetSymbolAddress((void**)&Qwr,    g_Qwr);

    const long offNonDet = 0;
    const long offActDet = (long)Bc * C * Nd;
    const long offActAim = 2 * offActDet;
    const long offCw     = offActAim + (long)Bc * C * Na;

    cudaFuncSetAttribute(tgemm<0,0,1>, cudaFuncAttributeMaxDynamicSharedMemorySize, GSMEM);
    cudaFuncSetAttribute(tgemm<0,1,1>, cudaFuncAttributeMaxDynamicSharedMemorySize, GSMEM);
    cudaFuncSetAttribute(tgemm<0,2,1>, cudaFuncAttributeMaxDynamicSharedMemorySize, GSMEM);
    cudaFuncSetAttribute(tgemm<1,0,0>, cudaFuncAttributeMaxDynamicSharedMemorySize, GSMEM);
    cudaFuncSetAttribute(tgemm<2,0,0>, cudaFuncAttributeMaxDynamicSharedMemorySize, GSMEM);

    // T0: transpose + round activations; round weights
    transpose_k<<<dim3(Nd / 32, C / 32, Bc), dim3(32, 8)>>>(detect, detT, C, Nd);
    transpose_k<<<dim3(Na / 32, C / 32, Bc), dim3(32, 8)>>>(aim,    aimT, C, Na);
    {
        const int n4 = (Ci * C) / 4;
        round_k<<<(n4 + 255) / 256, 256>>>(g_w,  gwr,  n4);
        round_k<<<(n4 + 255) / 256, 256>>>(th_w, thwr, n4);
        round_k<<<(n4 + 255) / 256, 256>>>(ph_w, phwr, n4);
        round_k<<<(n4 + 255) / 256, 256>>>(W_w,  Wwr,  n4);
        round_k<<<(n4 + 255) / 256, 256>>>(Q_w,  Qwr,  n4);
    }

    // G1: d_x[Ci,Nd] = gwr * detT^T + g_b[m]          (rounded out)
    tgemm<0,1,1><<<dim3(Nd/128, Ci/128, Bc), 256, GSMEM>>>(
        gwr, detT, dx, C, Nd, 0, (long)Nd*C, (long)Ci*Nd, 1.f,
        g_b, nullptr, nullptr, nullptr, nullptr, 0, nullptr, nullptr);
    // G2: phi_x[Nd,Ci] = detT * phwr^T + ph_b[n]      (rounded out)
    tgemm<0,2,1><<<dim3(Ci/128, Nd/128, Bc), 256, GSMEM>>>(
        detT, phwr, phx, C, Ci, (long)Nd*C, 0, (long)Nd*Ci, 1.f,
        nullptr, ph_b, nullptr, nullptr, nullptr, 0, nullptr, nullptr);
    // G3: a_x[Ci,Na] = gwr * aimT^T + g_b[m]          (rounded out)
    tgemm<0,1,1><<<dim3(Na/128, Ci/128, Bc), 256, GSMEM>>>(
        gwr, aimT, ax, C, Na, 0, (long)Na*C, (long)Ci*Na, 1.f,
        g_b, nullptr, nullptr, nullptr, nullptr, 0, nullptr, nullptr);
    // G4: theta_x[Na,Ci] = aimT * thwr^T + th_b[n]    (rounded out)
    tgemm<0,2,1><<<dim3(Ci/128, Na/128, Bc), 256, GSMEM>>>(
        aimT, thwr, thx, C, Ci, (long)Na*C, 0, (long)Na*Ci, 1.f,
        nullptr, th_b, nullptr, nullptr, nullptr, 0, nullptr, nullptr);
    // G5: f[Na,Nd] = theta * phi^T                    (rounded out)
    tgemm<0,0,1><<<dim3(Nd/128, Na/128, Bc), 256, GSMEM>>>(
        thx, phx, fm, Ci, Nd, (long)Na*Ci, (long)Nd*Ci, (long)Na*Nd, 1.f,
        nullptr, nullptr, nullptr, nullptr, nullptr, 0, nullptr, nullptr);
    // G5b: fT[Nd,Na] = phi * theta^T                  (rounded out)
    tgemm<0,0,1><<<dim3(Na/128, Nd/128, Bc), 256, GSMEM>>>(
        phx, thx, fT, Ci, Na, (long)Nd*Ci, (long)Na*Ci, (long)Nd*Na, 1.f,
        nullptr, nullptr, nullptr, nullptr, nullptr, 0, nullptr, nullptr);
    // G6: nap[Na,Ci] = (1/Nd) f * d_x^T               (rounded out)
    tgemm<0,0,1><<<dim3(Ci/128, Na/128, Bc), 256, GSMEM>>>(
        fm, dx, nap, Nd, Ci, (long)Na*Nd, (long)Ci*Nd, (long)Na*Ci, 1.f/Nd,
        nullptr, nullptr, nullptr, nullptr, nullptr, 0, nullptr, nullptr);
    // G7: ndp[Nd,Ci] = (1/Na) fT * a_x^T              (rounded out)
    tgemm<0,0,1><<<dim3(Ci/128, Nd/128, Bc), 256, GSMEM>>>(
        fT, ax, ndp, Na, Ci, (long)Nd*Na, (long)Ci*Na, (long)Nd*Ci, 1.f/Na,
        nullptr, nullptr, nullptr, nullptr, nullptr, 0, nullptr, nullptr);
    // G8: non_aim[C,Na] = bn(Wwr * nap^T + W_b) + aim (full precision out)
    tgemm<1,0,0><<<dim3(Na/128, C/128, Bc), 256, GSMEM>>>(
        Wwr, nap, nonaim, Ci, Na, 0, (long)Na*Ci, (long)C*Na, 1.f,
        W_b, nullptr, W_bn_g, W_bn_b, aim, (long)C*Na, nullptr, nullptr);
    // pool + gate
    pool_k<<<(Bc * C) / 8, 256>>>(nonaim, pooled);
    gate_k<<<Bc, 256>>>(pooled, m1_w, m1_b, m2_w, m2_b, out + offCw);
    // G9: non_det[C,Nd] = bn(Qwr * ndp^T + Q_b) + detect ; act_det fused
    tgemm<2,0,0><<<dim3(Nd/128, C/128, Bc), 256, GSMEM>>>(
        Qwr, ndp, out + offNonDet, Ci, Nd, 0, (long)Nd*Ci, (long)C*Nd, 1.f,
        Q_b, nullptr, Q_bn_g, Q_bn_b, detect, (long)C*Nd,
        out + offCw, out + offActDet);
    // act_aim = non_aim * cw
    const long t4a = (long)Bc * C * Na / 4;
    scale_k<<<(unsigned)((t4a + 255) / 256), 256>>>(
        nonaim, out + offCw, out + offActAim, Na / 4, t4a);
}